// round 4
// baseline (speedup 1.0000x reference)
#include <cuda_runtime.h>
#include <cstdint>

#define NN 16384
#define DIN 512
#define DCAT 1024
#define E0MAX 524288
#define ETMAX (E0MAX + NN)

// ------------------------- scratch (static device globals) -------------------
__device__ float g_xh[NN * DCAT];       // 64 MB
__device__ float g_h2[NN * DCAT];       // 64 MB
__device__ float g_asrc[NN * 2];
__device__ float g_adst[NN * 2];
__device__ int   g_deg[NN];
__device__ int   g_rowstart[NN + 1];
__device__ int   g_cursor[NN];
__device__ int   g_csr_src[ETMAX];
__device__ float g_csr_e[ETMAX * 2];
__device__ float g_h3[NN * 128];
__device__ float g_h4[NN * 64];
__device__ float g_h5[NN * 3];
__device__ float g_sq[NN];
__device__ int   g_odd_nonzero;

// ------------------------- f32x2 helpers ------------------------------------
__device__ __forceinline__ unsigned long long pk2(float lo, float hi) {
    unsigned long long r;
    asm("mov.b64 %0,{%1,%2};" : "=l"(r) : "f"(lo), "f"(hi));
    return r;
}
__device__ __forceinline__ void fma2(unsigned long long& d, unsigned long long a, unsigned long long b) {
    asm("fma.rn.f32x2 %0,%1,%2,%0;" : "+l"(d) : "l"(a), "l"(b));
}
__device__ __forceinline__ float2 upk2(unsigned long long v) {
    float2 r;
    asm("mov.b64 {%0,%1},%2;" : "=f"(r.x), "=f"(r.y) : "l"(v));
    return r;
}

__device__ __forceinline__ float warpSum(float v) {
    #pragma unroll
    for (int o = 16; o > 0; o >>= 1) v += __shfl_down_sync(0xFFFFFFFFu, v, o);
    return v;
}

// ------------------------- init + dtype detect -------------------------------
__global__ void init_kernel() {
    int i = blockIdx.x * blockDim.x + threadIdx.x;
    if (i < NN) g_deg[i] = 0;
    if (i == 0) g_odd_nonzero = 0;
}

// If edge_index is int64, values < 16384 => every odd 32-bit word (high word)
// of the first E0 elements is zero. If int32, odd words are random node ids.
__global__ void detect_kernel(const int* __restrict__ ei32, int E0) {
    int i = blockIdx.x * blockDim.x + threadIdx.x;
    if (i < E0 && ei32[2 * i + 1] != 0) g_odd_nonzero = 1;
}

__device__ __forceinline__ void get_edge(const void* ei, int E0, int e, int& s, int& d) {
    if (e >= E0) { s = d = e - E0; return; }   // self-loop
    if (g_odd_nonzero == 0) {                  // int64
        const long long* p = (const long long*)ei;
        s = (int)p[e]; d = (int)p[E0 + e];
    } else {                                   // int32
        const int* p = (const int*)ei;
        s = p[e]; d = p[E0 + e];
    }
}

// ------------------------- generic SGEMM (f32x2) -----------------------------
template<int BM, int BN, int BK, int TM, int TN, bool RELU, bool HASBIAS>
__global__ void __launch_bounds__(256) sgemm_kernel(
    const float* __restrict__ A, const float* __restrict__ B,
    const float* __restrict__ bias, float* __restrict__ C,
    int M, int N, int K)
{
    __shared__ float As[BK][BM];
    __shared__ float Bs[BK][BN];
    const int tid = threadIdx.x;
    const int tx = tid % (BN / TN);
    const int ty = tid / (BN / TN);
    const int bm0 = blockIdx.y * BM;
    const int bn0 = blockIdx.x * BN;

    unsigned long long acc[TM][TN / 2];
    #pragma unroll
    for (int i = 0; i < TM; i++)
        #pragma unroll
        for (int j = 0; j < TN / 2; j++) acc[i][j] = 0ull;

    for (int k0 = 0; k0 < K; k0 += BK) {
        // load A tile (BM x BK), store transposed
        #pragma unroll
        for (int i = tid * 4; i < BM * BK; i += 256 * 4) {
            int r = i / BK, kk = i % BK;
            float4 v = *(const float4*)(A + (size_t)(bm0 + r) * K + k0 + kk);
            As[kk + 0][r] = v.x; As[kk + 1][r] = v.y;
            As[kk + 2][r] = v.z; As[kk + 3][r] = v.w;
        }
        // load B tile (BK x BN)
        #pragma unroll
        for (int i = tid * 4; i < BK * BN; i += 256 * 4) {
            int kk = i / BN, c = i % BN;
            *(float4*)&Bs[kk][c] = *(const float4*)(B + (size_t)(k0 + kk) * N + bn0 + c);
        }
        __syncthreads();
        #pragma unroll
        for (int kk = 0; kk < BK; kk++) {
            float ra[TM];
            unsigned long long rb[TN / 2];
            #pragma unroll
            for (int i = 0; i < TM; i += 4) {
                float4 v = *(const float4*)&As[kk][ty * TM + i];
                ra[i] = v.x; ra[i + 1] = v.y; ra[i + 2] = v.z; ra[i + 3] = v.w;
            }
            #pragma unroll
            for (int j = 0; j < TN; j += 4) {
                float4 v = *(const float4*)&Bs[kk][tx * TN + j];
                rb[j / 2] = pk2(v.x, v.y);
                rb[j / 2 + 1] = pk2(v.z, v.w);
            }
            #pragma unroll
            for (int i = 0; i < TM; i++) {
                unsigned long long av = pk2(ra[i], ra[i]);
                #pragma unroll
                for (int j = 0; j < TN / 2; j++) fma2(acc[i][j], av, rb[j]);
            }
        }
        __syncthreads();
    }
    #pragma unroll
    for (int i = 0; i < TM; i++) {
        int row = bm0 + ty * TM + i;
        #pragma unroll
        for (int j = 0; j < TN / 2; j++) {
            float2 v = upk2(acc[i][j]);
            int col = bn0 + tx * TN + 2 * j;
            if (HASBIAS) { v.x += bias[col]; v.y += bias[col + 1]; }
            if (RELU) { v.x = fmaxf(v.x, 0.f); v.y = fmaxf(v.y, 0.f); }
            *(float2*)(C + (size_t)row * N + col) = v;
        }
    }
}

// ------------------------- attention dots ------------------------------------
__global__ void attn_dot_kernel(const float* __restrict__ att_src,
                                const float* __restrict__ att_dst)
{
    int n = blockIdx.x;
    int t = threadIdx.x;
    const float* row = g_xh + (size_t)n * DCAT;
    float s0 = 0, s1 = 0, d0 = 0, d1 = 0;
    #pragma unroll
    for (int i = 0; i < 2; i++) {
        int c = t + i * 256;
        float v = row[c];
        s0 = fmaf(v, att_src[c], s0); d0 = fmaf(v, att_dst[c], d0);
        float w = row[c + 512];
        s1 = fmaf(w, att_src[c + 512], s1); d1 = fmaf(w, att_dst[c + 512], d1);
    }
    s0 = warpSum(s0); s1 = warpSum(s1); d0 = warpSum(d0); d1 = warpSum(d1);
    __shared__ float sm[8][4];
    int wid = t >> 5, ln = t & 31;
    if (ln == 0) { sm[wid][0] = s0; sm[wid][1] = s1; sm[wid][2] = d0; sm[wid][3] = d1; }
    __syncthreads();
    if (t < 4) {
        float acc = 0;
        #pragma unroll
        for (int w = 0; w < 8; w++) acc += sm[w][t];
        if (t == 0) g_asrc[2 * n] = acc;
        else if (t == 1) g_asrc[2 * n + 1] = acc;
        else if (t == 2) g_adst[2 * n] = acc;
        else g_adst[2 * n + 1] = acc;
    }
}

// ------------------------- CSR build -----------------------------------------
__global__ void deg_kernel(const void* __restrict__ ei, int E0) {
    int e = blockIdx.x * blockDim.x + threadIdx.x;
    int ET = E0 + NN;
    if (e >= ET) return;
    int s, d;
    get_edge(ei, E0, e, s, d);
    atomicAdd(&g_deg[d], 1);
}

__global__ void scan_kernel() {
    __shared__ int sm[256];
    int t = threadIdx.x;
    int base = t * 64;
    int sum = 0;
    for (int i = 0; i < 64; i++) sum += g_deg[base + i];
    sm[t] = sum;
    __syncthreads();
    for (int off = 1; off < 256; off <<= 1) {
        int v = (t >= off) ? sm[t - off] : 0;
        __syncthreads();
        if (t >= off) sm[t] += v;
        __syncthreads();
    }
    int run = (t == 0) ? 0 : sm[t - 1];
    for (int i = 0; i < 64; i++) {
        int dg = g_deg[base + i];
        g_rowstart[base + i] = run;
        g_cursor[base + i] = run;
        run += dg;
    }
    if (t == 255) g_rowstart[NN] = run;
}

__global__ void scatter_kernel(const void* __restrict__ ei, int E0) {
    int e = blockIdx.x * blockDim.x + threadIdx.x;
    int ET = E0 + NN;
    if (e >= ET) return;
    int s, d;
    get_edge(ei, E0, e, s, d);
    float l0 = g_asrc[2 * s] + g_adst[2 * d];
    float l1 = g_asrc[2 * s + 1] + g_adst[2 * d + 1];
    l0 = (l0 > 0.f) ? l0 : 0.2f * l0;   // leaky_relu(0.2)
    l1 = (l1 > 0.f) ? l1 : 0.2f * l1;
    float e0 = expf(l0);
    float e1 = expf(l1);
    int pos = atomicAdd(&g_cursor[d], 1);
    g_csr_src[pos] = s;
    g_csr_e[2 * pos] = e0;
    g_csr_e[2 * pos + 1] = e1;
}

// ------------------------- aggregation (one block per dst) -------------------
__global__ void __launch_bounds__(256) agg_kernel(const float* __restrict__ bias) {
    int d = blockIdx.x, t = threadIdx.x;
    int j0 = g_rowstart[d], j1 = g_rowstart[d + 1];

    // local softmax denominators (no max-subtraction needed: |logit| small)
    float z0 = 0, z1 = 0;
    for (int j = j0 + t; j < j1; j += 256) {
        z0 += g_csr_e[2 * j];
        z1 += g_csr_e[2 * j + 1];
    }
    z0 = warpSum(z0); z1 = warpSum(z1);
    __shared__ float sz[8][2];
    int wid = t >> 5, ln = t & 31;
    if (ln == 0) { sz[wid][0] = z0; sz[wid][1] = z1; }
    __syncthreads();
    if (t == 0) {
        float a = 0, b = 0;
        #pragma unroll
        for (int w = 0; w < 8; w++) { a += sz[w][0]; b += sz[w][1]; }
        sz[0][0] = 1.f / fmaxf(a, 1e-16f);
        sz[0][1] = 1.f / fmaxf(b, 1e-16f);
    }
    __syncthreads();
    float inv0 = sz[0][0], inv1 = sz[0][1];

    float a0 = 0, a1 = 0, a2 = 0, a3 = 0;
    for (int j = j0; j < j1; j++) {
        int s = g_csr_src[j];
        float w0 = g_csr_e[2 * j] * inv0;
        float w1 = g_csr_e[2 * j + 1] * inv1;
        const float* r = g_xh + (size_t)s * DCAT;
        a0 = fmaf(w0, r[t], a0);
        a1 = fmaf(w0, r[t + 256], a1);
        a2 = fmaf(w1, r[t + 512], a2);
        a3 = fmaf(w1, r[t + 768], a3);
    }
    float* o = g_h2 + (size_t)d * DCAT;
    o[t]       = fmaxf(a0 + bias[t], 0.f);
    o[t + 256] = fmaxf(a1 + bias[t + 256], 0.f);
    o[t + 512] = fmaxf(a2 + bias[t + 512], 0.f);
    o[t + 768] = fmaxf(a3 + bias[t + 768], 0.f);
}

// ------------------------- final layer + sq ----------------------------------
__global__ void head_kernel(const float* __restrict__ W2, const float* __restrict__ b2) {
    __shared__ float w[192];
    __shared__ float bb[3];
    int t = threadIdx.x;
    if (t < 192) w[t] = W2[t];
    if (t < 3) bb[t] = b2[t];
    __syncthreads();
    int n = blockIdx.x * blockDim.x + t;
    if (n >= NN) return;
    const float* r = g_h4 + (size_t)n * 64;
    float o0 = bb[0], o1 = bb[1], o2 = bb[2];
    #pragma unroll
    for (int k = 0; k < 64; k++) {
        float v = r[k];
        o0 = fmaf(v, w[3 * k + 0], o0);
        o1 = fmaf(v, w[3 * k + 1], o1);
        o2 = fmaf(v, w[3 * k + 2], o2);
    }
    g_h5[3 * n] = o0; g_h5[3 * n + 1] = o1; g_h5[3 * n + 2] = o2;
    // exact same op pattern as the dot in cdist => diagonal is exactly 0
    g_sq[n] = fmaf(o2, o2, fmaf(o1, o1, o0 * o0));
}

// ------------------------- cdist ---------------------------------------------
__global__ void __launch_bounds__(256) cdist_kernel(float* __restrict__ out) {
    __shared__ float4 sx[128];
    __shared__ float4 sy[128];
    int t = threadIdx.x;
    int bi = blockIdx.y * 128, bj = blockIdx.x * 128;
    if (t < 128) {
        int i = bi + t;
        sx[t] = make_float4(g_h5[3 * i], g_h5[3 * i + 1], g_h5[3 * i + 2], g_sq[i]);
    } else {
        int j = bj + t - 128;
        sy[t - 128] = make_float4(g_h5[3 * j], g_h5[3 * j + 1], g_h5[3 * j + 2], g_sq[j]);
    }
    __syncthreads();
    int ty = t >> 4, tx = t & 15;
    float4 a[8], b[8];
    #pragma unroll
    for (int u = 0; u < 8; u++) { a[u] = sx[ty * 8 + u]; b[u] = sy[tx * 8 + u]; }
    #pragma unroll
    for (int u = 0; u < 8; u++) {
        float4 ov[2];
        float* o = (float*)ov;
        #pragma unroll
        for (int v = 0; v < 8; v++) {
            float dot = fmaf(a[u].z, b[v].z, fmaf(a[u].y, b[v].y, a[u].x * b[v].x));
            float d2 = a[u].w + b[v].w - 2.f * dot;
            o[v] = (d2 > 0.f) ? sqrtf(d2) : 0.f;
        }
        float4* dst = (float4*)&out[(size_t)(bi + ty * 8 + u) * NN + bj + tx * 8];
        dst[0] = ov[0];
        dst[1] = ov[1];
    }
}

// ------------------------- launch --------------------------------------------
extern "C" void kernel_launch(void* const* d_in, const int* in_sizes, int n_in,
                              void* d_out, int out_size)
{
    const float* x       = (const float*)d_in[0];
    const void*  ei      = d_in[1];
    const float* W       = (const float*)d_in[2];
    const float* att_src = (const float*)d_in[3];
    const float* att_dst = (const float*)d_in[4];
    const float* bias    = (const float*)d_in[5];
    const float* Wa      = (const float*)d_in[6];
    const float* ba      = (const float*)d_in[7];
    const float* W1      = (const float*)d_in[8];
    const float* b1      = (const float*)d_in[9];
    const float* W2      = (const float*)d_in[10];
    const float* b2      = (const float*)d_in[11];
    float* out = (float*)d_out;

    int E0 = in_sizes[1] / 2;
    if (E0 > E0MAX) E0 = E0MAX;
    int ET = E0 + NN;

    float *p_xh, *p_h2, *p_h3, *p_h4;
    cudaGetSymbolAddress((void**)&p_xh, g_xh);
    cudaGetSymbolAddress((void**)&p_h2, g_h2);
    cudaGetSymbolAddress((void**)&p_h3, g_h3);
    cudaGetSymbolAddress((void**)&p_h4, g_h4);

    init_kernel<<<64, 256>>>();
    detect_kernel<<<(E0 + 255) / 256, 256>>>((const int*)ei, E0);

    // xh = x @ W
    sgemm_kernel<128, 128, 8, 8, 8, false, false>
        <<<dim3(DCAT / 128, NN / 128), 256>>>(x, W, nullptr, p_xh, NN, DCAT, DIN);

    attn_dot_kernel<<<NN, 256>>>(att_src, att_dst);

    deg_kernel<<<(ET + 255) / 256, 256>>>(ei, E0);
    scan_kernel<<<1, 256>>>();
    scatter_kernel<<<(ET + 255) / 256, 256>>>(ei, E0);
    agg_kernel<<<NN, 256>>>(bias);

    // h3 = relu(h2 @ Wa + ba)
    sgemm_kernel<128, 128, 8, 8, 8, true, true>
        <<<dim3(1, NN / 128), 256>>>(p_h2, Wa, ba, p_h3, NN, 128, DCAT);
    // h4 = relu(h3 @ W1 + b1)
    sgemm_kernel<128, 64, 8, 8, 4, true, true>
        <<<dim3(1, NN / 128), 256>>>(p_h3, W1, b1, p_h4, NN, 64, 128);

    head_kernel<<<NN / 256, 256>>>(W2, b2);
    cdist_kernel<<<dim3(NN / 128, NN / 128), 256>>>(out);
}

// round 6
// speedup vs baseline: 1.4327x; 1.4327x over previous
#include <cuda_runtime.h>
#include <cuda_bf16.h>
#include <cstdint>

#define NN 16384
#define DIN 512
#define DCAT 1024
#define E0MAX 524288
#define ETMAX (E0MAX + NN)

// ------------------------- scratch (static device globals) -------------------
__device__ float g_xh[NN * DCAT];               // 64 MB fp32 xh (attn + agg)
__device__ __nv_bfloat16 g_xhi[NN * DIN];       // split-bf16 x
__device__ __nv_bfloat16 g_xlo[NN * DIN];
__device__ __nv_bfloat16 g_wthi[DCAT * DIN];    // W^T split-bf16  [N=1024][K=512]
__device__ __nv_bfloat16 g_wtlo[DCAT * DIN];
__device__ __nv_bfloat16 g_h2hi[NN * DCAT];     // h2 split-bf16 (agg output)
__device__ __nv_bfloat16 g_h2lo[NN * DCAT];
__device__ __nv_bfloat16 g_wahi[128 * DCAT];    // Wa^T split-bf16 [N=128][K=1024]
__device__ __nv_bfloat16 g_walo[128 * DCAT];
__device__ float g_asrc[NN * 2];
__device__ float g_adst[NN * 2];
__device__ int   g_deg[NN];
__device__ int   g_rowstart[NN + 1];
__device__ int   g_cursor[NN];
__device__ int   g_csr_src[ETMAX];
__device__ float g_csr_e[ETMAX * 2];
__device__ float g_h3[NN * 128];
__device__ float g_h4[NN * 64];
__device__ float g_h5[NN * 3];
__device__ float g_sq[NN];
__device__ int   g_odd_nonzero;

// ------------------------- helpers -------------------------------------------
__device__ __forceinline__ uint32_t smem_u32(const void* p) {
    uint32_t a;
    asm("{ .reg .u64 t; cvta.to.shared.u64 t, %1; cvt.u32.u64 %0, t; }"
        : "=r"(a) : "l"(p));
    return a;
}
__device__ __forceinline__ void ldm_x4(uint32_t* r, uint32_t addr) {
    asm volatile("ldmatrix.sync.aligned.m8n8.x4.shared.b16 {%0,%1,%2,%3}, [%4];"
                 : "=r"(r[0]), "=r"(r[1]), "=r"(r[2]), "=r"(r[3]) : "r"(addr));
}
__device__ __forceinline__ void mma_bf16(float* c, const uint32_t* a, const uint32_t* b) {
    asm volatile("mma.sync.aligned.m16n8k16.row.col.f32.bf16.bf16.f32 "
                 "{%0,%1,%2,%3}, {%4,%5,%6,%7}, {%8,%9}, {%0,%1,%2,%3};"
                 : "+f"(c[0]), "+f"(c[1]), "+f"(c[2]), "+f"(c[3])
                 : "r"(a[0]), "r"(a[1]), "r"(a[2]), "r"(a[3]),
                   "r"(b[0]), "r"(b[1]));
}
__device__ __forceinline__ unsigned long long pk2(float lo, float hi) {
    unsigned long long r;
    asm("mov.b64 %0,{%1,%2};" : "=l"(r) : "f"(lo), "f"(hi));
    return r;
}
__device__ __forceinline__ void fma2(unsigned long long& d, unsigned long long a, unsigned long long b) {
    asm("fma.rn.f32x2 %0,%1,%2,%0;" : "+l"(d) : "l"(a), "l"(b));
}
__device__ __forceinline__ float2 upk2(unsigned long long v) {
    float2 r;
    asm("mov.b64 {%0,%1},%2;" : "=f"(r.x), "=f"(r.y) : "l"(v));
    return r;
}
__device__ __forceinline__ float warpSum(float v) {
    #pragma unroll
    for (int o = 16; o > 0; o >>= 1) v += __shfl_down_sync(0xFFFFFFFFu, v, o);
    return v;
}

// ------------------------- init + dtype detect -------------------------------
__global__ void init_kernel() {
    int i = blockIdx.x * blockDim.x + threadIdx.x;
    if (i < NN) g_deg[i] = 0;
    if (i == 0) g_odd_nonzero = 0;
}
__global__ void detect_kernel(const int* __restrict__ ei32, int E0) {
    int i = blockIdx.x * blockDim.x + threadIdx.x;
    if (i < E0 && ei32[2 * i + 1] != 0) g_odd_nonzero = 1;
}
__device__ __forceinline__ void get_edge(const void* ei, int E0, int e, int& s, int& d) {
    if (e >= E0) { s = d = e - E0; return; }
    if (g_odd_nonzero == 0) {
        const long long* p = (const long long*)ei;
        s = (int)p[e]; d = (int)p[E0 + e];
    } else {
        const int* p = (const int*)ei;
        s = p[e]; d = p[E0 + e];
    }
}

// ------------------------- split-bf16 conversion kernels ---------------------
__global__ void convert_split_kernel(const float* __restrict__ in,
                                     __nv_bfloat16* __restrict__ hi,
                                     __nv_bfloat16* __restrict__ lo, int n4) {
    int i = blockIdx.x * blockDim.x + threadIdx.x;
    if (i >= n4) return;
    float4 v = ((const float4*)in)[i];
    __nv_bfloat16 h0 = __float2bfloat16(v.x), h1 = __float2bfloat16(v.y);
    __nv_bfloat16 h2 = __float2bfloat16(v.z), h3 = __float2bfloat16(v.w);
    __nv_bfloat162* hp = (__nv_bfloat162*)hi;
    __nv_bfloat162* lp = (__nv_bfloat162*)lo;
    hp[2 * i]     = __nv_bfloat162(h0, h1);
    hp[2 * i + 1] = __nv_bfloat162(h2, h3);
    lp[2 * i]     = __nv_bfloat162(__float2bfloat16(v.x - __bfloat162float(h0)),
                                   __float2bfloat16(v.y - __bfloat162float(h1)));
    lp[2 * i + 1] = __nv_bfloat162(__float2bfloat16(v.z - __bfloat162float(h2)),
                                   __float2bfloat16(v.w - __bfloat162float(h3)));
}

// out[n*Kdim + k] = In[k*Ndim + n], split into hi/lo
__global__ void transpose_split_kernel(const float* __restrict__ in,
                                       __nv_bfloat16* __restrict__ hi,
                                       __nv_bfloat16* __restrict__ lo,
                                       int Kdim, int Ndim) {
    int i = blockIdx.x * blockDim.x + threadIdx.x;
    if (i >= Kdim * Ndim) return;
    int n = i / Kdim, k = i % Kdim;
    float v = in[(size_t)k * Ndim + n];
    __nv_bfloat16 h = __float2bfloat16(v);
    hi[i] = h;
    lo[i] = __float2bfloat16(v - __bfloat162float(h));
}

// ------------------------- mma.sync split-bf16 GEMM --------------------------
// D[M,N] = (Ahi+Alo)[M,K] @ (Bhi+Blo)[N,K]^T  (3-term split, fp32 accum)
// tile 128x128, BK=32. 8 warps: 2(n) x 4(m); warp tile 32m x 64n.
// smem rows padded to 40 bf16 (80B) => conflict-free ldmatrix phases.
__global__ void __launch_bounds__(256, 2) mma_gemm_kernel(
    const __nv_bfloat16* __restrict__ Ahi, const __nv_bfloat16* __restrict__ Alo,
    const __nv_bfloat16* __restrict__ Bhi, const __nv_bfloat16* __restrict__ Blo,
    const float* __restrict__ bias, float* __restrict__ C,
    int N, int K, int relu)
{
    __shared__ __nv_bfloat16 smem[4][128][40];  // Ahi, Alo, Bhi, Blo
    const int tid = threadIdx.x;
    const int lane = tid & 31, wid = tid >> 5;
    const int wx = wid & 1, wy = wid >> 1;
    const int wm = wy * 32, wn = wx * 64;
    const int bm0 = blockIdx.y * 128;
    const int bn0 = blockIdx.x * 128;

    float acc[2][8][4];
    #pragma unroll
    for (int mt = 0; mt < 2; mt++)
        #pragma unroll
        for (int nt = 0; nt < 8; nt++)
            #pragma unroll
            for (int q = 0; q < 4; q++) acc[mt][nt][q] = 0.f;

    const int nchunks = K >> 5;
    for (int c = 0; c < nchunks; c++) {
        const int kc = c << 5;
        // load 4 x (128 x 32) bf16 tiles: 2048 uint4 segments / 256 threads
        #pragma unroll
        for (int it = 0; it < 8; it++) {
            int idx = tid + it * 256;
            int mat = idx >> 9, rem = idx & 511;
            int r = rem >> 2, s = rem & 3;
            const __nv_bfloat16* g;
            if (mat == 0)      g = Ahi + (size_t)(bm0 + r) * K;
            else if (mat == 1) g = Alo + (size_t)(bm0 + r) * K;
            else if (mat == 2) g = Bhi + (size_t)(bn0 + r) * K;
            else               g = Blo + (size_t)(bn0 + r) * K;
            *(uint4*)&smem[mat][r][s * 8] = *(const uint4*)(g + kc + s * 8);
        }
        __syncthreads();
        #pragma unroll
        for (int kk = 0; kk < 32; kk += 16) {
            uint32_t ah[2][4], al[2][4];
            #pragma unroll
            for (int mt = 0; mt < 2; mt++) {
                int row = wm + mt * 16 + (lane & 15);
                int col = kk + ((lane >> 4) << 3);
                ldm_x4(ah[mt], smem_u32(&smem[0][row][col]));
                ldm_x4(al[mt], smem_u32(&smem[1][row][col]));
            }
            #pragma unroll
            for (int ntp = 0; ntp < 4; ntp++) {
                int t = lane >> 3;
                int row = wn + (2 * ntp + (t >> 1)) * 8 + (lane & 7);
                int col = kk + ((t & 1) << 3);
                uint32_t bh[4], bl[4];
                ldm_x4(bh, smem_u32(&smem[2][row][col]));
                ldm_x4(bl, smem_u32(&smem[3][row][col]));
                #pragma unroll
                for (int h = 0; h < 2; h++) {
                    int nt = 2 * ntp + h;
                    #pragma unroll
                    for (int mt = 0; mt < 2; mt++) {
                        mma_bf16(acc[mt][nt], ah[mt], bh + 2 * h);
                        mma_bf16(acc[mt][nt], ah[mt], bl + 2 * h);
                        mma_bf16(acc[mt][nt], al[mt], bh + 2 * h);
                    }
                }
            }
        }
        __syncthreads();
    }

    // epilogue: D[l/4][2(l%4)+j] = c0,c1 ; D[l/4+8][...] = c2,c3
    #pragma unroll
    for (int mt = 0; mt < 2; mt++) {
        int r0 = bm0 + wm + mt * 16 + (lane >> 2);
        #pragma unroll
        for (int nt = 0; nt < 8; nt++) {
            int col = bn0 + wn + nt * 8 + 2 * (lane & 3);
            float2 v0 = make_float2(acc[mt][nt][0], acc[mt][nt][1]);
            float2 v1 = make_float2(acc[mt][nt][2], acc[mt][nt][3]);
            if (bias) {
                float b0 = bias[col], b1 = bias[col + 1];
                v0.x += b0; v0.y += b1; v1.x += b0; v1.y += b1;
            }
            if (relu) {
                v0.x = fmaxf(v0.x, 0.f); v0.y = fmaxf(v0.y, 0.f);
                v1.x = fmaxf(v1.x, 0.f); v1.y = fmaxf(v1.y, 0.f);
            }
            *(float2*)(C + (size_t)r0 * N + col) = v0;
            *(float2*)(C + (size_t)(r0 + 8) * N + col) = v1;
        }
    }
}

// ------------------------- legacy f32x2 SGEMM (GEMM3 only) -------------------
template<int BM, int BN, int BK, int TM, int TN, bool RELU, bool HASBIAS>
__global__ void __launch_bounds__(256) sgemm_kernel(
    const float* __restrict__ A, const float* __restrict__ B,
    const float* __restrict__ bias, float* __restrict__ C,
    int M, int N, int K)
{
    __shared__ float As[BK][BM];
    __shared__ float Bs[BK][BN];
    const int tid = threadIdx.x;
    const int tx = tid % (BN / TN);
    const int ty = tid / (BN / TN);
    const int bm0 = blockIdx.y * BM;
    const int bn0 = blockIdx.x * BN;

    unsigned long long acc[TM][TN / 2];
    #pragma unroll
    for (int i = 0; i < TM; i++)
        #pragma unroll
        for (int j = 0; j < TN / 2; j++) acc[i][j] = 0ull;

    for (int k0 = 0; k0 < K; k0 += BK) {
        #pragma unroll
        for (int i = tid * 4; i < BM * BK; i += 256 * 4) {
            int r = i / BK, kk = i % BK;
            float4 v = *(const float4*)(A + (size_t)(bm0 + r) * K + k0 + kk);
            As[kk + 0][r] = v.x; As[kk + 1][r] = v.y;
            As[kk + 2][r] = v.z; As[kk + 3][r] = v.w;
        }
        #pragma unroll
        for (int i = tid * 4; i < BK * BN; i += 256 * 4) {
            int kk = i / BN, c = i % BN;
            *(float4*)&Bs[kk][c] = *(const float4*)(B + (size_t)(k0 + kk) * N + bn0 + c);
        }
        __syncthreads();
        #pragma unroll
        for (int kk = 0; kk < BK; kk++) {
            float ra[TM];
            unsigned long long rb[TN / 2];
            #pragma unroll
            for (int i = 0; i < TM; i += 4) {
                float4 v = *(const float4*)&As[kk][ty * TM + i];
                ra[i] = v.x; ra[i + 1] = v.y; ra[i + 2] = v.z; ra[i + 3] = v.w;
            }
            #pragma unroll
            for (int j = 0; j < TN; j += 4) {
                float4 v = *(const float4*)&Bs[kk][tx * TN + j];
                rb[j / 2] = pk2(v.x, v.y);
                rb[j / 2 + 1] = pk2(v.z, v.w);
            }
            #pragma unroll
            for (int i = 0; i < TM; i++) {
                unsigned long long av = pk2(ra[i], ra[i]);
                #pragma unroll
                for (int j = 0; j < TN / 2; j++) fma2(acc[i][j], av, rb[j]);
            }
        }
        __syncthreads();
    }
    #pragma unroll
    for (int i = 0; i < TM; i++) {
        int row = bm0 + ty * TM + i;
        #pragma unroll
        for (int j = 0; j < TN / 2; j++) {
            float2 v = upk2(acc[i][j]);
            int col = bn0 + tx * TN + 2 * j;
            if (HASBIAS) { v.x += bias[col]; v.y += bias[col + 1]; }
            if (RELU) { v.x = fmaxf(v.x, 0.f); v.y = fmaxf(v.y, 0.f); }
            *(float2*)(C + (size_t)row * N + col) = v;
        }
    }
}

// ------------------------- attention dots ------------------------------------
__global__ void attn_dot_kernel(const float* __restrict__ att_src,
                                const float* __restrict__ att_dst)
{
    int n = blockIdx.x;
    int t = threadIdx.x;
    const float* row = g_xh + (size_t)n * DCAT;
    float s0 = 0, s1 = 0, d0 = 0, d1 = 0;
    #pragma unroll
    for (int i = 0; i < 2; i++) {
        int c = t + i * 256;
        float v = row[c];
        s0 = fmaf(v, att_src[c], s0); d0 = fmaf(v, att_dst[c], d0);
        float w = row[c + 512];
        s1 = fmaf(w, att_src[c + 512], s1); d1 = fmaf(w, att_dst[c + 512], d1);
    }
    s0 = warpSum(s0); s1 = warpSum(s1); d0 = warpSum(d0); d1 = warpSum(d1);
    __shared__ float sm[8][4];
    int wid = t >> 5, ln = t & 31;
    if (ln == 0) { sm[wid][0] = s0; sm[wid][1] = s1; sm[wid][2] = d0; sm[wid][3] = d1; }
    __syncthreads();
    if (t < 4) {
        float acc = 0;
        #pragma unroll
        for (int w = 0; w < 8; w++) acc += sm[w][t];
        if (t == 0) g_asrc[2 * n] = acc;
        else if (t == 1) g_asrc[2 * n + 1] = acc;
        else if (t == 2) g_adst[2 * n] = acc;
        else g_adst[2 * n + 1] = acc;
    }
}

// ------------------------- CSR build -----------------------------------------
__global__ void deg_kernel(const void* __restrict__ ei, int E0) {
    int e = blockIdx.x * blockDim.x + threadIdx.x;
    int ET = E0 + NN;
    if (e >= ET) return;
    int s, d;
    get_edge(ei, E0, e, s, d);
    atomicAdd(&g_deg[d], 1);
}

__global__ void scan_kernel() {
    __shared__ int sm[256];
    int t = threadIdx.x;
    int base = t * 64;
    int sum = 0;
    for (int i = 0; i < 64; i++) sum += g_deg[base + i];
    sm[t] = sum;
    __syncthreads();
    for (int off = 1; off < 256; off <<= 1) {
        int v = (t >= off) ? sm[t - off] : 0;
        __syncthreads();
        if (t >= off) sm[t] += v;
        __syncthreads();
    }
    int run = (t == 0) ? 0 : sm[t - 1];
    for (int i = 0; i < 64; i++) {
        int dg = g_deg[base + i];
        g_rowstart[base + i] = run;
        g_cursor[base + i] = run;
        run += dg;
    }
    if (t == 255) g_rowstart[NN] = run;
}

__global__ void scatter_kernel(const void* __restrict__ ei, int E0) {
    int e = blockIdx.x * blockDim.x + threadIdx.x;
    int ET = E0 + NN;
    if (e >= ET) return;
    int s, d;
    get_edge(ei, E0, e, s, d);
    float l0 = g_asrc[2 * s] + g_adst[2 * d];
    float l1 = g_asrc[2 * s + 1] + g_adst[2 * d + 1];
    l0 = (l0 > 0.f) ? l0 : 0.2f * l0;
    l1 = (l1 > 0.f) ? l1 : 0.2f * l1;
    float e0 = expf(l0);
    float e1 = expf(l1);
    int pos = atomicAdd(&g_cursor[d], 1);
    g_csr_src[pos] = s;
    g_csr_e[2 * pos] = e0;
    g_csr_e[2 * pos + 1] = e1;
}

// --------- aggregation (one block per dst); writes h2 as split-bf16 ----------
__global__ void __launch_bounds__(256) agg_kernel(const float* __restrict__ bias) {
    int d = blockIdx.x, t = threadIdx.x;
    int j0 = g_rowstart[d], j1 = g_rowstart[d + 1];

    float z0 = 0, z1 = 0;
    for (int j = j0 + t; j < j1; j += 256) {
        z0 += g_csr_e[2 * j];
        z1 += g_csr_e[2 * j + 1];
    }
    z0 = warpSum(z0); z1 = warpSum(z1);
    __shared__ float sz[8][2];
    int wid = t >> 5, ln = t & 31;
    if (ln == 0) { sz[wid][0] = z0; sz[wid][1] = z1; }
    __syncthreads();
    if (t == 0) {
        float a = 0, b = 0;
        #pragma unroll
        for (int w = 0; w < 8; w++) { a += sz[w][0]; b += sz[w][1]; }
        sz[0][0] = 1.f / fmaxf(a, 1e-16f);
        sz[0][1] = 1.f / fmaxf(b, 1e-16f);
    }
    __syncthreads();
    float inv0 = sz[0][0], inv1 = sz[0][1];

    float4 acc = make_float4(0.f, 0.f, 0.f, 0.f);
    const int col = t * 4;
    const bool head0 = (t < 128);
    for (int j = j0; j < j1; j++) {
        int s = g_csr_src[j];
        float w = (head0 ? g_csr_e[2 * j] * inv0 : g_csr_e[2 * j + 1] * inv1);
        float4 v = *(const float4*)(g_xh + (size_t)s * DCAT + col);
        acc.x = fmaf(w, v.x, acc.x);
        acc.y = fmaf(w, v.y, acc.y);
        acc.z = fmaf(w, v.z, acc.z);
        acc.w = fmaf(w, v.w, acc.w);
    }
    size_t base = (size_t)d * DCAT + col;
    float r0 = fmaxf(acc.x + bias[col + 0], 0.f);
    float r1 = fmaxf(acc.y + bias[col + 1], 0.f);
    float r2 = fmaxf(acc.z + bias[col + 2], 0.f);
    float r3 = fmaxf(acc.w + bias[col + 3], 0.f);
    __nv_bfloat16 h0 = __float2bfloat16(r0), h1 = __float2bfloat16(r1);
    __nv_bfloat16 h2 = __float2bfloat16(r2), h3 = __float2bfloat16(r3);
    __nv_bfloat162* hp = (__nv_bfloat162*)(g_h2hi + base);
    __nv_bfloat162* lp = (__nv_bfloat162*)(g_h2lo + base);
    hp[0] = __nv_bfloat162(h0, h1);
    hp[1] = __nv_bfloat162(h2, h3);
    lp[0] = __nv_bfloat162(__float2bfloat16(r0 - __bfloat162float(h0)),
                           __float2bfloat16(r1 - __bfloat162float(h1)));
    lp[1] = __nv_bfloat162(__float2bfloat16(r2 - __bfloat162float(h2)),
                           __float2bfloat16(r3 - __bfloat162float(h3)));
}

// ------------------------- final layer + sq ----------------------------------
__global__ void head_kernel(const float* __restrict__ W2, const float* __restrict__ b2) {
    __shared__ float w[192];
    __shared__ float bb[3];
    int t = threadIdx.x;
    if (t < 192) w[t] = W2[t];
    if (t < 3) bb[t] = b2[t];
    __syncthreads();
    int n = blockIdx.x * blockDim.x + t;
    if (n >= NN) return;
    const float* r = g_h4 + (size_t)n * 64;
    float o0 = bb[0], o1 = bb[1], o2 = bb[2];
    #pragma unroll
    for (int k = 0; k < 64; k++) {
        float v = r[k];
        o0 = fmaf(v, w[3 * k + 0], o0);
        o1 = fmaf(v, w[3 * k + 1], o1);
        o2 = fmaf(v, w[3 * k + 2], o2);
    }
    g_h5[3 * n] = o0; g_h5[3 * n + 1] = o1; g_h5[3 * n + 2] = o2;
    g_sq[n] = fmaf(o2, o2, fmaf(o1, o1, o0 * o0));
}

// ------------------------- cdist ---------------------------------------------
__global__ void __launch_bounds__(256) cdist_kernel(float* __restrict__ out) {
    __shared__ float4 sx[128];
    __shared__ float4 sy[128];
    int t = threadIdx.x;
    int bi = blockIdx.y * 128, bj = blockIdx.x * 128;
    if (t < 128) {
        int i = bi + t;
        sx[t] = make_float4(g_h5[3 * i], g_h5[3 * i + 1], g_h5[3 * i + 2], g_sq[i]);
    } else {
        int j = bj + t - 128;
        sy[t - 128] = make_float4(g_h5[3 * j], g_h5[3 * j + 1], g_h5[3 * j + 2], g_sq[j]);
    }
    __syncthreads();
    int ty = t >> 4, tx = t & 15;
    float4 a[8], b[8];
    #pragma unroll
    for (int u = 0; u < 8; u++) { a[u] = sx[ty * 8 + u]; b[u] = sy[tx * 8 + u]; }
    #pragma unroll
    for (int u = 0; u < 8; u++) {
        float4 ov[2];
        float* o = (float*)ov;
        #pragma unroll
        for (int v = 0; v < 8; v++) {
            float dot = fmaf(a[u].z, b[v].z, fmaf(a[u].y, b[v].y, a[u].x * b[v].x));
            float d2 = a[u].w + b[v].w - 2.f * dot;
            o[v] = (d2 > 0.f) ? sqrtf(d2) : 0.f;
        }
        float4* dst = (float4*)&out[(size_t)(bi + ty * 8 + u) * NN + bj + tx * 8];
        dst[0] = ov[0];
        dst[1] = ov[1];
    }
}

// ------------------------- launch --------------------------------------------
extern "C" void kernel_launch(void* const* d_in, const int* in_sizes, int n_in,
                              void* d_out, int out_size)
{
    const float* x       = (const float*)d_in[0];
    const void*  ei      = d_in[1];
    const float* W       = (const float*)d_in[2];
    const float* att_src = (const float*)d_in[3];
    const float* att_dst = (const float*)d_in[4];
    const float* bias    = (const float*)d_in[5];
    const float* Wa      = (const float*)d_in[6];
    const float* ba      = (const float*)d_in[7];
    const float* W1      = (const float*)d_in[8];
    const float* b1      = (const float*)d_in[9];
    const float* W2      = (const float*)d_in[10];
    const float* b2      = (const float*)d_in[11];
    float* out = (float*)d_out;

    int E0 = in_sizes[1] / 2;
    if (E0 > E0MAX) E0 = E0MAX;
    int ET = E0 + NN;

    float *p_xh, *p_h3, *p_h4;
    __nv_bfloat16 *p_xhi, *p_xlo, *p_wthi, *p_wtlo, *p_h2hi, *p_h2lo, *p_wahi, *p_walo;
    cudaGetSymbolAddress((void**)&p_xh, g_xh);
    cudaGetSymbolAddress((void**)&p_h3, g_h3);
    cudaGetSymbolAddress((void**)&p_h4, g_h4);
    cudaGetSymbolAddress((void**)&p_xhi, g_xhi);
    cudaGetSymbolAddress((void**)&p_xlo, g_xlo);
    cudaGetSymbolAddress((void**)&p_wthi, g_wthi);
    cudaGetSymbolAddress((void**)&p_wtlo, g_wtlo);
    cudaGetSymbolAddress((void**)&p_h2hi, g_h2hi);
    cudaGetSymbolAddress((void**)&p_h2lo, g_h2lo);
    cudaGetSymbolAddress((void**)&p_wahi, g_wahi);
    cudaGetSymbolAddress((void**)&p_walo, g_walo);

    init_kernel<<<64, 256>>>();
    detect_kernel<<<(E0 + 255) / 256, 256>>>((const int*)ei, E0);

    // split-bf16 conversions
    convert_split_kernel<<<(NN * DIN / 4 + 255) / 256, 256>>>(x, p_xhi, p_xlo, NN * DIN / 4);
    transpose_split_kernel<<<(DCAT * DIN + 255) / 256, 256>>>(W, p_wthi, p_wtlo, DIN, DCAT);
    transpose_split_kernel<<<(128 * DCAT + 255) / 256, 256>>>(Wa, p_wahi, p_walo, DCAT, 128);

    // xh = x @ W  (mma.sync split-bf16)
    mma_gemm_kernel<<<dim3(DCAT / 128, NN / 128), 256>>>(
        p_xhi, p_xlo, p_wthi, p_wtlo, nullptr, p_xh, DCAT, DIN, 0);

    attn_dot_kernel<<<NN, 256>>>(att_src, att_dst);

    deg_kernel<<<(ET + 255) / 256, 256>>>(ei, E0);
    scan_kernel<<<1, 256>>>();
    scatter_kernel<<<(ET + 255) / 256, 256>>>(ei, E0);
    agg_kernel<<<NN, 256>>>(bias);

    // h3 = relu(h2 @ Wa + ba)  (mma.sync split-bf16)
    mma_gemm_kernel<<<dim3(1, NN / 128), 256>>>(
        p_h2hi, p_h2lo, p_wahi, p_walo, ba, p_h3, 128, DCAT, 1);

    // h4 = relu(h3 @ W1 + b1)  (f32x2, tiny)
    sgemm_kernel<128, 64, 8, 8, 4, true, true>
        <<<dim3(1, NN / 128), 256>>>(p_h3, W1, b1, p_h4, NN, 64, 128);

    head_kernel<<<NN / 256, 256>>>(W2, b2);
    cdist_kernel<<<dim3(NN / 128, NN / 128), 256>>>(out);
}

// round 9
// speedup vs baseline: 1.4867x; 1.0377x over previous
#include <cuda_runtime.h>
#include <cuda_bf16.h>
#include <cstdint>

#define NN 16384
#define DIN 512
#define DCAT 1024
#define E0MAX 524288
#define ETMAX (E0MAX + NN)

// ------------------------- scratch (static device globals) -------------------
__device__ float g_xh[NN * DCAT];               // 64 MB fp32 xh (attn + agg)
__device__ __nv_bfloat16 g_xhi[NN * DIN];       // split-bf16 x
__device__ __nv_bfloat16 g_xlo[NN * DIN];
__device__ __nv_bfloat16 g_wthi[DCAT * DIN];    // W^T split-bf16  [N=1024][K=512]
__device__ __nv_bfloat16 g_wtlo[DCAT * DIN];
__device__ __nv_bfloat16 g_h2hi[NN * DCAT];     // h2 split-bf16 (agg output)
__device__ __nv_bfloat16 g_h2lo[NN * DCAT];
__device__ __nv_bfloat16 g_wahi[128 * DCAT];    // Wa^T split-bf16 [N=128][K=1024]
__device__ __nv_bfloat16 g_walo[128 * DCAT];
__device__ float g_asrc[NN * 2];
__device__ float g_adst[NN * 2];
__device__ int   g_deg[NN];
__device__ int   g_rowstart[NN + 1];
__device__ int   g_cursor[NN];
__device__ int   g_csr_src[ETMAX];
__device__ float g_csr_e[ETMAX * 2];
__device__ float g_h3[NN * 128];
__device__ float g_h4[NN * 64];
__device__ float g_h5[NN * 3];
__device__ float g_sq[NN];
__device__ int   g_odd_nonzero;

// ------------------------- helpers -------------------------------------------
__device__ __forceinline__ uint32_t smem_u32(const void* p) {
    uint32_t a;
    asm("{ .reg .u64 t; cvta.to.shared.u64 t, %1; cvt.u32.u64 %0, t; }"
        : "=r"(a) : "l"(p));
    return a;
}
__device__ __forceinline__ void ldm_x4(uint32_t* r, uint32_t addr) {
    asm volatile("ldmatrix.sync.aligned.m8n8.x4.shared.b16 {%0,%1,%2,%3}, [%4];"
                 : "=r"(r[0]), "=r"(r[1]), "=r"(r[2]), "=r"(r[3]) : "r"(addr));
}
__device__ __forceinline__ void mma_bf16(float* c, const uint32_t* a, const uint32_t* b) {
    asm volatile("mma.sync.aligned.m16n8k16.row.col.f32.bf16.bf16.f32 "
                 "{%0,%1,%2,%3}, {%4,%5,%6,%7}, {%8,%9}, {%0,%1,%2,%3};"
                 : "+f"(c[0]), "+f"(c[1]), "+f"(c[2]), "+f"(c[3])
                 : "r"(a[0]), "r"(a[1]), "r"(a[2]), "r"(a[3]),
                   "r"(b[0]), "r"(b[1]));
}
__device__ __forceinline__ void cp_async16(uint32_t saddr, const void* g) {
    asm volatile("cp.async.cg.shared.global [%0], [%1], 16;"
                 :: "r"(saddr), "l"(g));
}
#define CP_COMMIT() asm volatile("cp.async.commit_group;" ::: "memory")
#define CP_WAIT(n)  asm volatile("cp.async.wait_group %0;" :: "n"(n) : "memory")

__device__ __forceinline__ unsigned long long pk2(float lo, float hi) {
    unsigned long long r;
    asm("mov.b64 %0,{%1,%2};" : "=l"(r) : "f"(lo), "f"(hi));
    return r;
}
__device__ __forceinline__ void fma2(unsigned long long& d, unsigned long long a, unsigned long long b) {
    asm("fma.rn.f32x2 %0,%1,%2,%0;" : "+l"(d) : "l"(a), "l"(b));
}
__device__ __forceinline__ float2 upk2(unsigned long long v) {
    float2 r;
    asm("mov.b64 {%0,%1},%2;" : "=f"(r.x), "=f"(r.y) : "l"(v));
    return r;
}
__device__ __forceinline__ float warpSum(float v) {
    #pragma unroll
    for (int o = 16; o > 0; o >>= 1) v += __shfl_down_sync(0xFFFFFFFFu, v, o);
    return v;
}

// ------------------------- init + dtype detect -------------------------------
__global__ void init_kernel() {
    int i = blockIdx.x * blockDim.x + threadIdx.x;
    if (i < NN) g_deg[i] = 0;
    if (i == 0) g_odd_nonzero = 0;
}
__global__ void detect_kernel(const int* __restrict__ ei32, int E0) {
    int i = blockIdx.x * blockDim.x + threadIdx.x;
    if (i < E0 && ei32[2 * i + 1] != 0) g_odd_nonzero = 1;
}
__device__ __forceinline__ void get_edge(const void* ei, int E0, int e, int& s, int& d) {
    if (e >= E0) { s = d = e - E0; return; }
    if (g_odd_nonzero == 0) {
        const long long* p = (const long long*)ei;
        s = (int)p[e]; d = (int)p[E0 + e];
    } else {
        const int* p = (const int*)ei;
        s = p[e]; d = p[E0 + e];
    }
}

// ------------------------- split-bf16 conversion kernels ---------------------
__global__ void convert_split_kernel(const float* __restrict__ in,
                                     __nv_bfloat16* __restrict__ hi,
                                     __nv_bfloat16* __restrict__ lo, int n4) {
    int i = blockIdx.x * blockDim.x + threadIdx.x;
    if (i >= n4) return;
    float4 v = ((const float4*)in)[i];
    __nv_bfloat16 h0 = __float2bfloat16(v.x), h1 = __float2bfloat16(v.y);
    __nv_bfloat16 h2 = __float2bfloat16(v.z), h3 = __float2bfloat16(v.w);
    __nv_bfloat162* hp = (__nv_bfloat162*)hi;
    __nv_bfloat162* lp = (__nv_bfloat162*)lo;
    hp[2 * i]     = __nv_bfloat162(h0, h1);
    hp[2 * i + 1] = __nv_bfloat162(h2, h3);
    lp[2 * i]     = __nv_bfloat162(__float2bfloat16(v.x - __bfloat162float(h0)),
                                   __float2bfloat16(v.y - __bfloat162float(h1)));
    lp[2 * i + 1] = __nv_bfloat162(__float2bfloat16(v.z - __bfloat162float(h2)),
                                   __float2bfloat16(v.w - __bfloat162float(h3)));
}

// out[n*Kdim + k] = In[k*Ndim + n], split into hi/lo
__global__ void transpose_split_kernel(const float* __restrict__ in,
                                       __nv_bfloat16* __restrict__ hi,
                                       __nv_bfloat16* __restrict__ lo,
                                       int Kdim, int Ndim) {
    int i = blockIdx.x * blockDim.x + threadIdx.x;
    if (i >= Kdim * Ndim) return;
    int n = i / Kdim, k = i % Kdim;
    float v = in[(size_t)k * Ndim + n];
    __nv_bfloat16 h = __float2bfloat16(v);
    hi[i] = h;
    lo[i] = __float2bfloat16(v - __bfloat162float(h));
}

// ------------------------- mma.sync split-bf16 GEMM --------------------------
// D[M,N] = (Ahi+Alo)[M,K] @ (Bhi+Blo)[N,K]^T  (3-term split, fp32 accum)
// tile 128x128, BK=32. 8 warps: 2(n) x 4(m); warp tile 32m x 64n.
// 2-stage cp.async pipeline; smem rows padded to 40 bf16 (80B).
#define SM_IDX(st, mat, r, c) ((((st) * 4 + (mat)) * 128 + (r)) * 40 + (c))

__global__ void __launch_bounds__(256, 2) mma_gemm_kernel(
    const __nv_bfloat16* __restrict__ Ahi, const __nv_bfloat16* __restrict__ Alo,
    const __nv_bfloat16* __restrict__ Bhi, const __nv_bfloat16* __restrict__ Blo,
    const float* __restrict__ bias, float* __restrict__ C,
    int N, int K, int relu)
{
    extern __shared__ __nv_bfloat16 smem[];   // [2][4][128][40]
    const int tid = threadIdx.x;
    const int lane = tid & 31, wid = tid >> 5;
    const int wx = wid & 1, wy = wid >> 1;
    const int wm = wy * 32, wn = wx * 64;
    const int bm0 = blockIdx.y * 128;
    const int bn0 = blockIdx.x * 128;

    float acc[2][8][4];
    #pragma unroll
    for (int mt = 0; mt < 2; mt++)
        #pragma unroll
        for (int nt = 0; nt < 8; nt++)
            #pragma unroll
            for (int q = 0; q < 4; q++) acc[mt][nt][q] = 0.f;

    const int nchunks = K >> 5;

    // per-thread fixed load slots: 8 x 16B segments
    const __nv_bfloat16* gbase[4] = {
        Ahi + (size_t)bm0 * K, Alo + (size_t)bm0 * K,
        Bhi + (size_t)bn0 * K, Blo + (size_t)bn0 * K };

    auto load_chunk = [&](int c, int st) {
        const int kc = c << 5;
        #pragma unroll
        for (int it = 0; it < 8; it++) {
            int idx = tid + it * 256;
            int mat = idx >> 9, rem = idx & 511;
            int r = rem >> 2, s4 = rem & 3;
            cp_async16(smem_u32(&smem[SM_IDX(st, mat, r, s4 * 8)]),
                       gbase[mat] + (size_t)r * K + kc + s4 * 8);
        }
    };

    load_chunk(0, 0);
    CP_COMMIT();

    for (int c = 0; c < nchunks; c++) {
        const int cur = c & 1;
        if (c + 1 < nchunks) {
            load_chunk(c + 1, cur ^ 1);
            CP_COMMIT();
            CP_WAIT(1);
        } else {
            CP_WAIT(0);
        }
        __syncthreads();

        #pragma unroll
        for (int kk = 0; kk < 32; kk += 16) {
            uint32_t ah[2][4], al[2][4];
            #pragma unroll
            for (int mt = 0; mt < 2; mt++) {
                int row = wm + mt * 16 + (lane & 15);
                int col = kk + ((lane >> 4) << 3);
                ldm_x4(ah[mt], smem_u32(&smem[SM_IDX(cur, 0, row, col)]));
                ldm_x4(al[mt], smem_u32(&smem[SM_IDX(cur, 1, row, col)]));
            }
            #pragma unroll
            for (int ntp = 0; ntp < 4; ntp++) {
                int t = lane >> 3;
                int row = wn + (2 * ntp + (t >> 1)) * 8 + (lane & 7);
                int col = kk + ((t & 1) << 3);
                uint32_t bh[4], bl[4];
                ldm_x4(bh, smem_u32(&smem[SM_IDX(cur, 2, row, col)]));
                ldm_x4(bl, smem_u32(&smem[SM_IDX(cur, 3, row, col)]));
                #pragma unroll
                for (int h = 0; h < 2; h++) {
                    int nt = 2 * ntp + h;
                    #pragma unroll
                    for (int mt = 0; mt < 2; mt++) {
                        mma_bf16(acc[mt][nt], ah[mt], bh + 2 * h);
                        mma_bf16(acc[mt][nt], ah[mt], bl + 2 * h);
                        mma_bf16(acc[mt][nt], al[mt], bh + 2 * h);
                    }
                }
            }
        }
        __syncthreads();
    }

    // epilogue: D[l/4][2(l%4)+j] = c0,c1 ; D[l/4+8][...] = c2,c3
    #pragma unroll
    for (int mt = 0; mt < 2; mt++) {
        int r0 = bm0 + wm + mt * 16 + (lane >> 2);
        #pragma unroll
        for (int nt = 0; nt < 8; nt++) {
            int col = bn0 + wn + nt * 8 + 2 * (lane & 3);
            float2 v0 = make_float2(acc[mt][nt][0], acc[mt][nt][1]);
            float2 v1 = make_float2(acc[mt][nt][2], acc[mt][nt][3]);
            if (bias) {
                float b0 = bias[col], b1 = bias[col + 1];
                v0.x += b0; v0.y += b1; v1.x += b0; v1.y += b1;
            }
            if (relu) {
                v0.x = fmaxf(v0.x, 0.f); v0.y = fmaxf(v0.y, 0.f);
                v1.x = fmaxf(v1.x, 0.f); v1.y = fmaxf(v1.y, 0.f);
            }
            *(float2*)(C + (size_t)r0 * N + col) = v0;
            *(float2*)(C + (size_t)(r0 + 8) * N + col) = v1;
        }
    }
}

// ------------------------- legacy f32x2 SGEMM (GEMM3 only) -------------------
template<int BM, int BN, int BK, int TM, int TN, bool RELU, bool HASBIAS>
__global__ void __launch_bounds__(256) sgemm_kernel(
    const float* __restrict__ A, const float* __restrict__ B,
    const float* __restrict__ bias, float* __restrict__ C,
    int M, int N, int K)
{
    __shared__ float As[BK][BM];
    __shared__ float Bs[BK][BN];
    const int tid = threadIdx.x;
    const int tx = tid % (BN / TN);
    const int ty = tid / (BN / TN);
    const int bm0 = blockIdx.y * BM;
    const int bn0 = blockIdx.x * BN;

    unsigned long long acc[TM][TN / 2];
    #pragma unroll
    for (int i = 0; i < TM; i++)
        #pragma unroll
        for (int j = 0; j < TN / 2; j++) acc[i][j] = 0ull;

    for (int k0 = 0; k0 < K; k0 += BK) {
        #pragma unroll
        for (int i = tid * 4; i < BM * BK; i += 256 * 4) {
            int r = i / BK, kk = i % BK;
            float4 v = *(const float4*)(A + (size_t)(bm0 + r) * K + k0 + kk);
            As[kk + 0][r] = v.x; As[kk + 1][r] = v.y;
            As[kk + 2][r] = v.z; As[kk + 3][r] = v.w;
        }
        #pragma unroll
        for (int i = tid * 4; i < BK * BN; i += 256 * 4) {
            int kk = i / BN, c = i % BN;
            *(float4*)&Bs[kk][c] = *(const float4*)(B + (size_t)(k0 + kk) * N + bn0 + c);
        }
        __syncthreads();
        #pragma unroll
        for (int kk = 0; kk < BK; kk++) {
            float ra[TM];
            unsigned long long rb[TN / 2];
            #pragma unroll
            for (int i = 0; i < TM; i += 4) {
                float4 v = *(const float4*)&As[kk][ty * TM + i];
                ra[i] = v.x; ra[i + 1] = v.y; ra[i + 2] = v.z; ra[i + 3] = v.w;
            }
            #pragma unroll
            for (int j = 0; j < TN; j += 4) {
                float4 v = *(const float4*)&Bs[kk][tx * TN + j];
                rb[j / 2] = pk2(v.x, v.y);
                rb[j / 2 + 1] = pk2(v.z, v.w);
            }
            #pragma unroll
            for (int i = 0; i < TM; i++) {
                unsigned long long av = pk2(ra[i], ra[i]);
                #pragma unroll
                for (int j = 0; j < TN / 2; j++) fma2(acc[i][j], av, rb[j]);
            }
        }
        __syncthreads();
    }
    #pragma unroll
    for (int i = 0; i < TM; i++) {
        int row = bm0 + ty * TM + i;
        #pragma unroll
        for (int j = 0; j < TN / 2; j++) {
            float2 v = upk2(acc[i][j]);
            int col = bn0 + tx * TN + 2 * j;
            if (HASBIAS) { v.x += bias[col]; v.y += bias[col + 1]; }
            if (RELU) { v.x = fmaxf(v.x, 0.f); v.y = fmaxf(v.y, 0.f); }
            *(float2*)(C + (size_t)row * N + col) = v;
        }
    }
}

// ------------------------- attention dots (float4) ---------------------------
__global__ void attn_dot_kernel(const float* __restrict__ att_src,
                                const float* __restrict__ att_dst)
{
    int n = blockIdx.x;
    int t = threadIdx.x;
    float4 v = ((const float4*)(g_xh + (size_t)n * DCAT))[t];
    float4 as = ((const float4*)att_src)[t];
    float4 ad = ((const float4*)att_dst)[t];
    float s = fmaf(v.w, as.w, fmaf(v.z, as.z, fmaf(v.y, as.y, v.x * as.x)));
    float d = fmaf(v.w, ad.w, fmaf(v.z, ad.z, fmaf(v.y, ad.y, v.x * ad.x)));
    s = warpSum(s); d = warpSum(d);
    __shared__ float sm[8][2];
    int wid = t >> 5, ln = t & 31;
    if (ln == 0) { sm[wid][0] = s; sm[wid][1] = d; }
    __syncthreads();
    if (t < 4) {
        // t=0: asrc h0 (warps 0-3), t=1: asrc h1 (warps 4-7), t=2/3: adst h0/h1
        int h = t & 1;
    int which = t >> 1;
        float acc = 0;
        #pragma unroll
        for (int w = 0; w < 4; w++) acc += sm[h * 4 + w][which];
        if (which == 0) g_asrc[2 * n + h] = acc;
        else            g_adst[2 * n + h] = acc;
    }
}

// ------------------------- CSR build -----------------------------------------
__global__ void deg_kernel(const void* __restrict__ ei, int E0) {
    int e = blockIdx.x * blockDim.x + threadIdx.x;
    int ET = E0 + NN;
    if (e >= ET) return;
    int s, d;
    get_edge(ei, E0, e, s, d);
    atomicAdd(&g_deg[d], 1);
}

__global__ void scan_kernel() {
    __shared__ int sm[256];
    int t = threadIdx.x;
    int base = t * 64;
    int sum = 0;
    for (int i = 0; i < 64; i++) sum += g_deg[base + i];
    sm[t] = sum;
    __syncthreads();
    for (int off = 1; off < 256; off <<= 1) {
        int v = (t >= off) ? sm[t - off] : 0;
        __syncthreads();
        if (t >= off) sm[t] += v;
        __syncthreads();
    }
    int run = (t == 0) ? 0 : sm[t - 1];
    for (int i = 0; i < 64; i++) {
        int dg = g_deg[base + i];
        g_rowstart[base + i] = run;
        g_cursor[base + i] = run;
        run += dg;
    }
    if (t == 255) g_rowstart[NN] = run;
}

__global__ void scatter_kernel(const void* __restrict__ ei, int E0) {
    int e = blockIdx.x * blockDim.x + threadIdx.x;
    int ET = E0 + NN;
    if (e >= ET) return;
    int s, d;
    get_edge(ei, E0, e, s, d);
    float l0 = g_asrc[2 * s] + g_adst[2 * d];
    float l1 = g_asrc[2 * s + 1] + g_adst[2 * d + 1];
    l0 = (l0 > 0.f) ? l0 : 0.2f * l0;
    l1 = (l1 > 0.f) ? l1 : 0.2f * l1;
    float e0 = expf(l0);
    float e1 = expf(l1);
    int pos = atomicAdd(&g_cursor[d], 1);
    g_csr_src[pos] = s;
    g_csr_e[2 * pos] = e0;
    g_csr_e[2 * pos + 1] = e1;
}

// --------- aggregation (one block per dst); writes h2 as split-bf16 ----------
// Edges staged in smem per 256-chunk; gather unrolled x4 for MLP.
__global__ void __launch_bounds__(256) agg_kernel(const float* __restrict__ bias) {
    int d = blockIdx.x, t = threadIdx.x;
    int j0 = g_rowstart[d], j1 = g_rowstart[d + 1];

    float z0 = 0, z1 = 0;
    for (int j = j0 + t; j < j1; j += 256) {
        float2 e = ((const float2*)g_csr_e)[j];
        z0 += e.x; z1 += e.y;
    }
    z0 = warpSum(z0); z1 = warpSum(z1);
    __shared__ float sz[8][2];
    int wid = t >> 5, ln = t & 31;
    if (ln == 0) { sz[wid][0] = z0; sz[wid][1] = z1; }
    __syncthreads();
    if (t == 0) {
        float a = 0, b = 0;
        #pragma unroll
        for (int w = 0; w < 8; w++) { a += sz[w][0]; b += sz[w][1]; }
        sz[0][0] = 1.f / fmaxf(a, 1e-16f);
        sz[0][1] = 1.f / fmaxf(b, 1e-16f);
    }
    __syncthreads();
    float inv0 = sz[0][0], inv1 = sz[0][1];

    __shared__ int   ssrc[256];
    __shared__ float swgt[256];          // per-thread head weight not possible; store raw pair
    __shared__ float swgt2[256];

    float4 acc = make_float4(0.f, 0.f, 0.f, 0.f);
    const int col = t * 4;
    const bool head0 = (t < 128);

    for (int jc = j0; jc < j1; jc += 256) {
        int cnt = min(256, j1 - jc);
        __syncthreads();
        if (t < cnt) {
            ssrc[t] = g_csr_src[jc + t];
            float2 e = ((const float2*)g_csr_e)[jc + t];
            swgt[t] = e.x * inv0;
            swgt2[t] = e.y * inv1;
        }
        __syncthreads();
        int jj = 0;
        for (; jj + 4 <= cnt; jj += 4) {
            int s0 = ssrc[jj], s1 = ssrc[jj + 1], s2 = ssrc[jj + 2], s3 = ssrc[jj + 3];
            float w0 = head0 ? swgt[jj] : swgt2[jj];
            float w1 = head0 ? swgt[jj + 1] : swgt2[jj + 1];
            float w2 = head0 ? swgt[jj + 2] : swgt2[jj + 2];
            float w3 = head0 ? swgt[jj + 3] : swgt2[jj + 3];
            float4 v0 = *(const float4*)(g_xh + (size_t)s0 * DCAT + col);
            float4 v1 = *(const float4*)(g_xh + (size_t)s1 * DCAT + col);
            float4 v2 = *(const float4*)(g_xh + (size_t)s2 * DCAT + col);
            float4 v3 = *(const float4*)(g_xh + (size_t)s3 * DCAT + col);
            acc.x = fmaf(w0, v0.x, acc.x); acc.y = fmaf(w0, v0.y, acc.y);
            acc.z = fmaf(w0, v0.z, acc.z); acc.w = fmaf(w0, v0.w, acc.w);
            acc.x = fmaf(w1, v1.x, acc.x); acc.y = fmaf(w1, v1.y, acc.y);
            acc.z = fmaf(w1, v1.z, acc.z); acc.w = fmaf(w1, v1.w, acc.w);
            acc.x = fmaf(w2, v2.x, acc.x); acc.y = fmaf(w2, v2.y, acc.y);
            acc.z = fmaf(w2, v2.z, acc.z); acc.w = fmaf(w2, v2.w, acc.w);
            acc.x = fmaf(w3, v3.x, acc.x); acc.y = fmaf(w3, v3.y, acc.y);
            acc.z = fmaf(w3, v3.z, acc.z); acc.w = fmaf(w3, v3.w, acc.w);
        }
        for (; jj < cnt; jj++) {
            int s = ssrc[jj];
            float w = head0 ? swgt[jj] : swgt2[jj];
            float4 v = *(const float4*)(g_xh + (size_t)s * DCAT + col);
            acc.x = fmaf(w, v.x, acc.x); acc.y = fmaf(w, v.y, acc.y);
            acc.z = fmaf(w, v.z, acc.z); acc.w = fmaf(w, v.w, acc.w);
        }
    }

    size_t base = (size_t)d * DCAT + col;
    float r0 = fmaxf(acc.x + bias[col + 0], 0.f);
    float r1 = fmaxf(acc.y + bias[col + 1], 0.f);
    float r2 = fmaxf(acc.z + bias[col + 2], 0.f);
    float r3 = fmaxf(acc.w + bias[col + 3], 0.f);
    __nv_bfloat16 h0 = __float2bfloat16(r0), h1 = __float2bfloat16(r1);
    __nv_bfloat16 h2 = __float2bfloat16(r2), h3 = __float2bfloat16(r3);
    __nv_bfloat162* hp = (__nv_bfloat162*)(g_h2hi + base);
    __nv_bfloat162* lp = (__nv_bfloat162*)(g_h2lo + base);
    hp[0] = __nv_bfloat162(h0, h1);
    hp[1] = __nv_bfloat162(h2, h3);
    lp[0] = __nv_bfloat162(__float2bfloat16(r0 - __bfloat162float(h0)),
                           __float2bfloat16(r1 - __bfloat162float(h1)));
    lp[1] = __nv_bfloat162(__float2bfloat16(r2 - __bfloat162float(h2)),
                           __float2bfloat16(r3 - __bfloat162float(h3)));
}

// ------------------------- final layer + sq ----------------------------------
__global__ void head_kernel(const float* __restrict__ W2, const float* __restrict__ b2) {
    __shared__ float w[192];
    __shared__ float bb[3];
    int t = threadIdx.x;
    if (t < 192) w[t] = W2[t];
    if (t < 3) bb[t] = b2[t];
    __syncthreads();
    int n = blockIdx.x * blockDim.x + t;
    if (n >= NN) return;
    const float* r = g_h4 + (size_t)n * 64;
    float o0 = bb[0], o1 = bb[1], o2 = bb[2];
    #pragma unroll
    for (int k = 0; k < 64; k++) {
        float v = r[k];
        o0 = fmaf(v, w[3 * k + 0], o0);
        o1 = fmaf(v, w[3 * k + 1], o1);
        o2 = fmaf(v, w[3 * k + 2], o2);
    }
    g_h5[3 * n] = o0; g_h5[3 * n + 1] = o1; g_h5[3 * n + 2] = o2;
    g_sq[n] = fmaf(o2, o2, fmaf(o1, o1, o0 * o0));
}

// ------------------------- cdist ---------------------------------------------
__global__ void __launch_bounds__(256) cdist_kernel(float* __restrict__ out) {
    __shared__ float4 sx[128];
    __shared__ float4 sy[128];
    int t = threadIdx.x;
    int bi = blockIdx.y * 128, bj = blockIdx.x * 128;
    if (t < 128) {
        int i = bi + t;
        sx[t] = make_float4(g_h5[3 * i], g_h5[3 * i + 1], g_h5[3 * i + 2], g_sq[i]);
    } else {
        int j = bj + t - 128;
        sy[t - 128] = make_float4(g_h5[3 * j], g_h5[3 * j + 1], g_h5[3 * j + 2], g_sq[j]);
    }
    __syncthreads();
    int ty = t >> 4, tx = t & 15;
    float4 a[8], b[8];
    #pragma unroll
    for (int u = 0; u < 8; u++) { a[u] = sx[ty * 8 + u]; b[u] = sy[tx * 8 + u]; }
    #pragma unroll
    for (int u = 0; u < 8; u++) {
        float4 ov[2];
        float* o = (float*)ov;
        #pragma unroll
        for (int v = 0; v < 8; v++) {
            float dot = fmaf(a[u].z, b[v].z, fmaf(a[u].y, b[v].y, a[u].x * b[v].x));
            float d2 = a[u].w + b[v].w - 2.f * dot;
            o[v] = (d2 > 0.f) ? sqrtf(d2) : 0.f;
        }
        float4* dst = (float4*)&out[(size_t)(bi + ty * 8 + u) * NN + bj + tx * 8];
        dst[0] = ov[0];
        dst[1] = ov[1];
    }
}

// ------------------------- launch --------------------------------------------
extern "C" void kernel_launch(void* const* d_in, const int* in_sizes, int n_in,
                              void* d_out, int out_size)
{
    const float* x       = (const float*)d_in[0];
    const void*  ei      = d_in[1];
    const float* W       = (const float*)d_in[2];
    const float* att_src = (const float*)d_in[3];
    const float* att_dst = (const float*)d_in[4];
    const float* bias    = (const float*)d_in[5];
    const float* Wa      = (const float*)d_in[6];
    const float* ba      = (const float*)d_in[7];
    const float* W1      = (const float*)d_in[8];
    const float* b1      = (const float*)d_in[9];
    const float* W2      = (const float*)d_in[10];
    const float* b2      = (const float*)d_in[11];
    float* out = (float*)d_out;

    int E0 = in_sizes[1] / 2;
    if (E0 > E0MAX) E0 = E0MAX;
    int ET = E0 + NN;

    float *p_xh, *p_h3, *p_h4;
    __nv_bfloat16 *p_xhi, *p_xlo, *p_wthi, *p_wtlo, *p_h2hi, *p_h2lo, *p_wahi, *p_walo;
    cudaGetSymbolAddress((void**)&p_xh, g_xh);
    cudaGetSymbolAddress((void**)&p_h3, g_h3);
    cudaGetSymbolAddress((void**)&p_h4, g_h4);
    cudaGetSymbolAddress((void**)&p_xhi, g_xhi);
    cudaGetSymbolAddress((void**)&p_xlo, g_xlo);
    cudaGetSymbolAddress((void**)&p_wthi, g_wthi);
    cudaGetSymbolAddress((void**)&p_wtlo, g_wtlo);
    cudaGetSymbolAddress((void**)&p_h2hi, g_h2hi);
    cudaGetSymbolAddress((void**)&p_h2lo, g_h2lo);
    cudaGetSymbolAddress((void**)&p_wahi, g_wahi);
    cudaGetSymbolAddress((void**)&p_walo, g_walo);

    const int SMEM_DYN = 2 * 4 * 128 * 40 * 2;   // 81920 B
    cudaFuncSetAttribute(mma_gemm_kernel,
                         cudaFuncAttributeMaxDynamicSharedMemorySize, SMEM_DYN);

    init_kernel<<<64, 256>>>();
    detect_kernel<<<(E0 + 255) / 256, 256>>>((const int*)ei, E0);

    // split-bf16 conversions
    convert_split_kernel<<<(NN * DIN / 4 + 255) / 256, 256>>>(x, p_xhi, p_xlo, NN * DIN / 4);
    transpose_split_kernel<<<(DCAT * DIN + 255) / 256, 256>>>(W, p_wthi, p_wtlo, DIN, DCAT);
    transpose_split_kernel<<<(128 * DCAT + 255) / 256, 256>>>(Wa, p_wahi, p_walo, DCAT, 128);

    // xh = x @ W  (mma.sync split-bf16, 2-stage cp.async pipeline)
    mma_gemm_kernel<<<dim3(DCAT / 128, NN / 128), 256, SMEM_DYN>>>(
        p_xhi, p_xlo, p_wthi, p_wtlo, nullptr, p_xh, DCAT, DIN, 0);

    attn_dot_kernel<<<NN, 256>>>(att_src, att_dst);

    deg_kernel<<<(ET + 255) / 256, 256>>>(ei, E0);
    scan_kernel<<<1, 256>>>();
    scatter_kernel<<<(ET + 255) / 256, 256>>>(ei, E0);
    agg_kernel<<<NN, 256>>>(bias);

    // h3 = relu(h2 @ Wa + ba)  (mma.sync split-bf16)
    mma_gemm_kernel<<<dim3(1, NN / 128), 256, SMEM_DYN>>>(
        p_h2hi, p_h2lo, p_wahi, p_walo, ba, p_h3, 128, DCAT, 1);

    // h4 = relu(h3 @ W1 + b1)  (f32x2, tiny)
    sgemm_kernel<128, 64, 8, 8, 4, true, true>
        <<<dim3(1, NN / 128), 256>>>(p_h3, W1, b1, p_h4, NN, 64, 128);

    head_kernel<<<NN / 256, 256>>>(W2, b2);
    cdist_kernel<<<dim3(NN / 128, NN / 128), 256>>>(out);
}